// round 4
// baseline (speedup 1.0000x reference)
#include <cuda_runtime.h>
#include <cuda_bf16.h>
#include <math_constants.h>
#include <cstdint>

#define BATCH 16
#define CDIM  512
#define NPOS  4096      // 64*64
#define O3    1536      // 3*HID
#define HID   512
#define HEADS 8
#define DH    64
#define EPSV  1e-5f
#define QSCALE 0.125f   // DH^-0.5

typedef __nv_bfloat16 bf16;

// ---------------- scratch (device globals; no allocations allowed) ---------
__device__ float g_mean [BATCH * NPOS];
__device__ float g_rstd [BATCH * NPOS];
__device__ bf16  g_xt_h [(size_t)BATCH * NPOS * CDIM];   // x normalized, channel-last, hi
__device__ bf16  g_xt_l [(size_t)BATCH * NPOS * CDIM];   // lo
__device__ float g_qkv  [(size_t)BATCH * O3   * NPOS];   // channel-major
__device__ float g_ctx  [BATCH * HEADS * DH * DH];
__device__ bf16  g_at_h [(size_t)BATCH * NPOS * HID];    // attn out, channel-last, hi
__device__ bf16  g_at_l [(size_t)BATCH * NPOS * HID];
__device__ float g_outpre[(size_t)BATCH * CDIM * NPOS];  // pre-final-LN, channel-major
__device__ bf16  g_wq_h [O3  * CDIM];
__device__ bf16  g_wq_l [O3  * CDIM];
__device__ bf16  g_wo_h [HID * CDIM];
__device__ bf16  g_wo_l [HID * CDIM];

// ======================= mma.sync / cp.async helpers (sm_80+) ==============
__device__ __forceinline__ uint32_t smem_to_u32(const void* p) {
    uint32_t a;
    asm("{ .reg .u64 t; cvta.to.shared.u64 t, %1; cvt.u32.u64 %0, t; }"
        : "=r"(a) : "l"(p));
    return a;
}
__device__ __forceinline__ void ldsm_x4(uint32_t& r0, uint32_t& r1,
                                        uint32_t& r2, uint32_t& r3, uint32_t addr) {
    asm volatile("ldmatrix.sync.aligned.m8n8.x4.shared.b16 {%0,%1,%2,%3}, [%4];"
        : "=r"(r0), "=r"(r1), "=r"(r2), "=r"(r3) : "r"(addr));
}
__device__ __forceinline__ void mma16816(float* d, const uint32_t* a,
                                         uint32_t b0, uint32_t b1) {
    asm volatile(
        "mma.sync.aligned.m16n8k16.row.col.f32.bf16.bf16.f32 "
        "{%0,%1,%2,%3},{%4,%5,%6,%7},{%8,%9},{%0,%1,%2,%3};"
        : "+f"(d[0]), "+f"(d[1]), "+f"(d[2]), "+f"(d[3])
        : "r"(a[0]), "r"(a[1]), "r"(a[2]), "r"(a[3]), "r"(b0), "r"(b1));
}
__device__ __forceinline__ void cp_async16(uint32_t saddr, const void* gaddr) {
    asm volatile("cp.async.cg.shared.global [%0], [%1], 16;"
        :: "r"(saddr), "l"(gaddr));
}
#define CP_COMMIT()  asm volatile("cp.async.commit_group;" ::: "memory")
#define CP_WAIT(N)   asm volatile("cp.async.wait_group %0;" :: "n"(N) : "memory")

// ======================= split-bf16 tensor-core GEMM (pipelined) ===========
// C[b, bm+r, bn+c] = sum_k A[bm+r, k] * B[b, bn+c, k]  (+ bias[bm+r])
// A: [M_total, 512] bf16 hi/lo K-contiguous. B: [b, 4096, 512] bf16 hi/lo.
#define KC  32
#define LDT 40                       // KC + 8 pad (bf16); row stride 80 B
#define TILE_B16  (128 * LDT)        // 5120 bf16 = 10240 B per operand tile
#define STAGE_B16 (4 * TILE_B16)     // Ah,Al,Bh,Bl per stage
#define GEMM_SMEM (2 * STAGE_B16 * 2)  // 81920 B (2 stages)
#define NKC (CDIM / KC)              // 16

__global__ __launch_bounds__(256, 2) void gemm_mma(
    const bf16* __restrict__ Ah, const bf16* __restrict__ Al,
    const bf16* __restrict__ Bh, const bf16* __restrict__ Bl,
    float* __restrict__ C, const float* __restrict__ bias, int M_total)
{
    extern __shared__ bf16 sm[];
    uint32_t sbase = smem_to_u32(sm);

    int tid = threadIdx.x, wid = tid >> 5, lane = tid & 31;
    int b = blockIdx.z, bm = blockIdx.y * 128, bn = blockIdx.x * 128;
    int warp_m = (wid & 3) * 32;        // 4 warps along M
    int warp_n = (wid >> 2) * 64;       // 2 warps along N

    // global pointers in uint4 units (8 bf16); row pitch = 512/8 = 64
    const uint4* gAh = (const uint4*)Ah + (size_t)bm * 64;
    const uint4* gAl = (const uint4*)Al + (size_t)bm * 64;
    const uint4* gBh = (const uint4*)Bh + ((size_t)b * NPOS + bn) * 64;
    const uint4* gBl = (const uint4*)Bl + ((size_t)b * NPOS + bn) * 64;

    // per-thread load slots: 512 uint4 per tile -> 2 per thread per matrix
    int lrow0 = tid >> 2, lc0 = tid & 3;          // i = tid
    int lrow1 = (tid + 256) >> 2, lc1 = lc0;      // i = tid + 256

    float acc[2][8][4];
    #pragma unroll
    for (int mt = 0; mt < 2; mt++)
        #pragma unroll
        for (int nt = 0; nt < 8; nt++)
            #pragma unroll
            for (int f = 0; f < 4; f++) acc[mt][nt][f] = 0.f;

    auto load_stage = [&](int s, int kc) {
        uint32_t ub = sbase + (uint32_t)s * STAGE_B16 * 2;
        size_t go0 = (size_t)lrow0 * 64 + kc * 4 + lc0;
        size_t go1 = (size_t)lrow1 * 64 + kc * 4 + lc1;
        uint32_t so0 = ub + (uint32_t)(lrow0 * LDT + lc0 * 8) * 2;
        uint32_t so1 = ub + (uint32_t)(lrow1 * LDT + lc1 * 8) * 2;
        cp_async16(so0,                    gAh + go0);
        cp_async16(so1,                    gAh + go1);
        cp_async16(so0 + TILE_B16 * 2,     gAl + go0);
        cp_async16(so1 + TILE_B16 * 2,     gAl + go1);
        cp_async16(so0 + 2 * TILE_B16 * 2, gBh + go0);
        cp_async16(so1 + 2 * TILE_B16 * 2, gBh + go1);
        cp_async16(so0 + 3 * TILE_B16 * 2, gBl + go0);
        cp_async16(so1 + 3 * TILE_B16 * 2, gBl + go1);
    };

    load_stage(0, 0);
    CP_COMMIT();

    for (int kc = 0; kc < NKC; kc++) {
        if (kc + 1 < NKC) {
            load_stage((kc + 1) & 1, kc + 1);
            CP_COMMIT();
            CP_WAIT(1);                 // current stage's group done
        } else {
            CP_WAIT(0);
        }
        __syncthreads();

        uint32_t ub  = sbase + (uint32_t)(kc & 1) * STAGE_B16 * 2;
        uint32_t uAh = ub;
        uint32_t uAl = ub + TILE_B16 * 2;
        uint32_t uBh = ub + 2 * TILE_B16 * 2;
        uint32_t uBl = ub + 3 * TILE_B16 * 2;

        #pragma unroll
        for (int kk = 0; kk < 2; kk++) {
            uint32_t ah[2][4], al[2][4];
            #pragma unroll
            for (int mt = 0; mt < 2; mt++) {
                uint32_t off = 2 * (uint32_t)((warp_m + mt * 16 + (lane & 15)) * LDT
                                              + kk * 16 + (lane >> 4) * 8);
                ldsm_x4(ah[mt][0], ah[mt][1], ah[mt][2], ah[mt][3], uAh + off);
                ldsm_x4(al[mt][0], al[mt][1], al[mt][2], al[mt][3], uAl + off);
            }
            #pragma unroll
            for (int nt2 = 0; nt2 < 4; nt2++) {
                uint32_t off = 2 * (uint32_t)((warp_n + nt2 * 16 + (lane & 15)) * LDT
                                              + kk * 16 + (lane >> 4) * 8);
                uint32_t bh0, bh1, bh2, bh3, bl0, bl1, bl2, bl3;
                ldsm_x4(bh0, bh1, bh2, bh3, uBh + off);
                ldsm_x4(bl0, bl1, bl2, bl3, uBl + off);
                #pragma unroll
                for (int mt = 0; mt < 2; mt++) {
                    mma16816(acc[mt][nt2 * 2 + 0], ah[mt], bh0, bh2);
                    mma16816(acc[mt][nt2 * 2 + 1], ah[mt], bh1, bh3);
                    mma16816(acc[mt][nt2 * 2 + 0], ah[mt], bl0, bl2);
                    mma16816(acc[mt][nt2 * 2 + 1], ah[mt], bl1, bl3);
                    mma16816(acc[mt][nt2 * 2 + 0], al[mt], bh0, bh2);
                    mma16816(acc[mt][nt2 * 2 + 1], al[mt], bh1, bh3);
                }
            }
        }
        __syncthreads();   // protect stage (kc&1) from next prefetch overwrite
    }

    // writeout: c-frag rows r, r+8; cols 2*(lane%4), +1  -> float2 stores
    #pragma unroll
    for (int mt = 0; mt < 2; mt++) {
        int r0 = bm + warp_m + mt * 16 + (lane >> 2);
        float bb0 = bias ? bias[r0] : 0.f;
        float bb8 = bias ? bias[r0 + 8] : 0.f;
        #pragma unroll
        for (int nt = 0; nt < 8; nt++) {
            int col = bn + warp_n + nt * 8 + 2 * (lane & 3);
            float2 v0 = make_float2(acc[mt][nt][0] + bb0, acc[mt][nt][1] + bb0);
            float2 v1 = make_float2(acc[mt][nt][2] + bb8, acc[mt][nt][3] + bb8);
            *(float2*)&C[((size_t)b * M_total + r0    ) * NPOS + col] = v0;
            *(float2*)&C[((size_t)b * M_total + r0 + 8) * NPOS + col] = v1;
        }
    }
}

// ---------------- LN stats: mean/rstd over C per (b,p) ---------------------
__global__ __launch_bounds__(256) void ln_stats_kernel(
    const float* __restrict__ in, float* __restrict__ mean, float* __restrict__ rstd)
{
    int gid = blockIdx.x * 256 + threadIdx.x;
    int b = gid >> 12, p = gid & (NPOS - 1);
    const float* ip = in + (size_t)b * CDIM * NPOS + p;
    float s = 0.f, s2 = 0.f;
    #pragma unroll 8
    for (int c = 0; c < CDIM; c++) {
        float v = ip[(size_t)c * NPOS];
        s += v; s2 += v * v;
    }
    float m = s * (1.f / CDIM);
    float var = s2 * (1.f / CDIM) - m * m;
    mean[gid] = m;
    rstd[gid] = rsqrtf(var + EPSV);
}

// ---------------- normalize + transpose to channel-last, split bf16 --------
__global__ __launch_bounds__(256) void norm_transpose_kernel(
    const float* __restrict__ x, const float* __restrict__ g,
    const float* __restrict__ mean, const float* __restrict__ rstd,
    bf16* __restrict__ xh, bf16* __restrict__ xl)
{
    __shared__ float t[64][65];
    int b = blockIdx.z, c0 = blockIdx.y * 64, p0 = blockIdx.x * 64;
    int tid = threadIdx.x;
    #pragma unroll
    for (int l = 0; l < 16; l++) {
        int i = l * 256 + tid;
        int c = i >> 6, p = i & 63;
        float v = x[((size_t)b * CDIM + c0 + c) * NPOS + p0 + p];
        int sp = b * NPOS + p0 + p;
        t[p][c] = (v - mean[sp]) * rstd[sp] * g[c0 + c];
    }
    __syncthreads();
    #pragma unroll
    for (int l = 0; l < 16; l++) {
        int i = l * 256 + tid;
        int p = i >> 6, c = i & 63;
        float v = t[p][c];
        bf16 h = __float2bfloat16(v);
        bf16 lo = __float2bfloat16(v - __bfloat162float(h));
        size_t o = ((size_t)b * NPOS + p0 + p) * CDIM + c0 + c;
        xh[o] = h; xl[o] = lo;
    }
}

// ---------------- fp32 -> bf16 hi/lo split (weights) -----------------------
__global__ __launch_bounds__(256) void split_bf16_kernel(
    const float* __restrict__ w, bf16* __restrict__ h, bf16* __restrict__ l, int n)
{
    int i = blockIdx.x * 256 + threadIdx.x;
    if (i < n) {
        float v = w[i];
        bf16 hi = __float2bfloat16(v);
        h[i] = hi;
        l[i] = __float2bfloat16(v - __bfloat162float(hi));
    }
}

// ---------------- softmax over head-dim (axis=-2) for q, then *scale ------
__global__ __launch_bounds__(256) void softmax_q_kernel(float* __restrict__ qkv)
{
    int gid = blockIdx.x * 256 + threadIdx.x;
    int p = gid & (NPOS - 1);
    int bm = gid >> 12;
    int m = bm & (HEADS - 1);
    int b = bm >> 3;
    float* base = qkv + (size_t)b * O3 * NPOS + (size_t)(m * DH) * NPOS + p;

    float v[DH];
    float mx = -CUDART_INF_F;
    #pragma unroll
    for (int i = 0; i < DH; i++) {
        v[i] = base[(size_t)i * NPOS];
        mx = fmaxf(mx, v[i]);
    }
    float s = 0.f;
    #pragma unroll
    for (int i = 0; i < DH; i++) { v[i] = __expf(v[i] - mx); s += v[i]; }
    float r = QSCALE / s;
    #pragma unroll
    for (int i = 0; i < DH; i++) base[(size_t)i * NPOS] = v[i] * r;
}

// ---------------- softmax over n (axis=-1) for k ---------------------------
__device__ __forceinline__ float warp_max(float v) {
    #pragma unroll
    for (int o = 16; o > 0; o >>= 1) v = fmaxf(v, __shfl_xor_sync(0xffffffffu, v, o));
    return v;
}
__device__ __forceinline__ float warp_sum(float v) {
    #pragma unroll
    for (int o = 16; o > 0; o >>= 1) v += __shfl_xor_sync(0xffffffffu, v, o);
    return v;
}

__global__ __launch_bounds__(256) void softmax_k_kernel(float* __restrict__ qkv)
{
    __shared__ float red[8];
    int row = blockIdx.x;
    int i = row & (DH - 1);
    int m = (row >> 6) & (HEADS - 1);
    int b = row >> 9;
    float* base = qkv + (size_t)b * O3 * NPOS + (size_t)(HID + m * DH + i) * NPOS;
    int t = threadIdx.x;
    int lane = t & 31, wid = t >> 5;

    float v[16];
    float mx = -CUDART_INF_F;
    #pragma unroll
    for (int u = 0; u < 16; u++) {
        v[u] = base[u * 256 + t];
        mx = fmaxf(mx, v[u]);
    }
    mx = warp_max(mx);
    if (lane == 0) red[wid] = mx;
    __syncthreads();
    mx = warp_max((lane < 8) ? red[lane] : -CUDART_INF_F);
    mx = __shfl_sync(0xffffffffu, mx, 0);

    float s = 0.f;
    #pragma unroll
    for (int u = 0; u < 16; u++) { v[u] = __expf(v[u] - mx); s += v[u]; }
    s = warp_sum(s);
    __syncthreads();
    if (lane == 0) red[wid] = s;
    __syncthreads();
    s = warp_sum((lane < 8) ? red[lane] : 0.f);
    s = __shfl_sync(0xffffffffu, s, 0);

    float r = 1.f / s;
    #pragma unroll
    for (int u = 0; u < 16; u++) base[u * 256 + t] = v[u] * r;
}

// ---------------- zero ------------------------------------------------------
__global__ __launch_bounds__(256) void zero_kernel(float* __restrict__ p, int n)
{
    int i = blockIdx.x * 256 + threadIdx.x;
    if (i < n) p[i] = 0.f;
}

// ---------------- context[b,m,i,j] = sum_n k[i,n] * v[j,n] -----------------
#define NSPLIT 4
__global__ __launch_bounds__(256) void context_kernel(
    const float* __restrict__ qkv, float* __restrict__ ctx)
{
    __shared__ float Ks[64][65];
    __shared__ float Vs[64][65];
    int bm = blockIdx.x;
    int m = bm & (HEADS - 1);
    int b = bm >> 3;
    const float* kbase = qkv + (size_t)b * O3 * NPOS + (size_t)(HID     + m * DH) * NPOS;
    const float* vbase = qkv + (size_t)b * O3 * NPOS + (size_t)(2 * HID + m * DH) * NPOS;
    int tid = threadIdx.x;
    int ti = tid & 15, tj = tid >> 4;

    float acc[4][4];
    #pragma unroll
    for (int a = 0; a < 4; a++)
        #pragma unroll
        for (int c = 0; c < 4; c++) acc[a][c] = 0.f;

    int nsplit = NPOS / NSPLIT;
    int nstart = blockIdx.y * nsplit;
    for (int nc = 0; nc < nsplit; nc += 64) {
        int nb = nstart + nc;
        #pragma unroll
        for (int l = 0; l < 16; l++) {
            int idx = l * 256 + tid;
            int i = idx >> 6, nn = idx & 63;
            Ks[nn][i] = kbase[(size_t)i * NPOS + nb + nn];
            Vs[nn][i] = vbase[(size_t)i * NPOS + nb + nn];
        }
        __syncthreads();
        #pragma unroll 8
        for (int nn = 0; nn < 64; nn++) {
            float ka[4], vb[4];
            #pragma unroll
            for (int a = 0; a < 4; a++) ka[a] = Ks[nn][ti * 4 + a];
            #pragma unroll
            for (int c = 0; c < 4; c++) vb[c] = Vs[nn][tj * 4 + c];
            #pragma unroll
            for (int a = 0; a < 4; a++)
                #pragma unroll
                for (int c = 0; c < 4; c++) acc[a][c] += ka[a] * vb[c];
        }
        __syncthreads();
    }
    #pragma unroll
    for (int a = 0; a < 4; a++)
        #pragma unroll
        for (int c = 0; c < 4; c++)
            atomicAdd(&ctx[(size_t)bm * DH * DH + (ti * 4 + a) * DH + (tj * 4 + c)],
                      acc[a][c]);
}

// -------- attn_out -> channel-last bf16 hi/lo (for GEMM2 B operand) --------
// attn_t[b, n, m*64+j] = sum_i ctx[b,m,i,j] * q[b,m,i,n]
__global__ __launch_bounds__(128) void attnout_kernel(
    const float* __restrict__ qkv, const float* __restrict__ ctx,
    bf16* __restrict__ ath, bf16* __restrict__ atl)
{
    __shared__ float cs[DH][DH];        // 16 KB
    __shared__ float stage[128][64];    // 32 KB (rotated to dodge bank conflicts)
    int bm = blockIdx.y;
    int m = bm & (HEADS - 1);
    int b = bm >> 3;
    const float* qbase = qkv + (size_t)b * O3 * NPOS + (size_t)(m * DH) * NPOS;
    int tid = threadIdx.x;

    #pragma unroll
    for (int l = 0; l < 32; l++)
        ((float*)cs)[l * 128 + tid] = ctx[(size_t)bm * DH * DH + l * 128 + tid];
    __syncthreads();

    int n0 = blockIdx.x * 128;
    int n = n0 + tid;
    float accj[DH];
    #pragma unroll
    for (int j = 0; j < DH; j++) accj[j] = 0.f;

    #pragma unroll 2
    for (int i = 0; i < DH; i++) {
        float qv = qbase[(size_t)i * NPOS + n];
        const float4* rowp = (const float4*)cs[i];
        #pragma unroll
        for (int j4 = 0; j4 < 16; j4++) {
            float4 c4 = rowp[j4];
            accj[j4 * 4 + 0] += c4.x * qv;
            accj[j4 * 4 + 1] += c4.y * qv;
            accj[j4 * 4 + 2] += c4.z * qv;
            accj[j4 * 4 + 3] += c4.w * qv;
        }
    }
    // rotated store: stage[tid][(j+tid)&63]
    #pragma unroll
    for (int j = 0; j < DH; j++) stage[tid][(j + tid) & 63] = accj[j];
    __syncthreads();

    // coalesced channel-last write with hi/lo split
    #pragma unroll
    for (int l = 0; l < 64; l++) {
        int idx = l * 128 + tid;
        int p = idx >> 6, j = idx & 63;
        float v = stage[p][(j + p) & 63];
        bf16 h = __float2bfloat16(v);
        bf16 lo = __float2bfloat16(v - __bfloat162float(h));
        size_t o = ((size_t)b * NPOS + n0 + p) * HID + m * DH + j;
        ath[o] = h; atl[o] = lo;
    }
}

// ---------------- final channel layernorm (channel-major, 2-pass) ----------
__global__ __launch_bounds__(256) void chan_ln_kernel(
    const float* __restrict__ in, const float* __restrict__ g,
    float* __restrict__ out)
{
    int gid = blockIdx.x * 256 + threadIdx.x;
    int b = gid >> 12;
    int p = gid & (NPOS - 1);
    const float* ip = in  + (size_t)b * CDIM * NPOS + p;
    float*       op = out + (size_t)b * CDIM * NPOS + p;

    float s = 0.f, s2 = 0.f;
    #pragma unroll 8
    for (int c = 0; c < CDIM; c++) {
        float v = ip[(size_t)c * NPOS];
        s += v; s2 += v * v;
    }
    float mean = s * (1.f / CDIM);
    float var = s2 * (1.f / CDIM) - mean * mean;
    float rstd = rsqrtf(var + EPSV);

    #pragma unroll 8
    for (int c = 0; c < CDIM; c++) {
        float v = ip[(size_t)c * NPOS];
        op[(size_t)c * NPOS] = (v - mean) * rstd * g[c];
    }
}

// ---------------- launch ---------------------------------------------------
extern "C" void kernel_launch(void* const* d_in, const int* in_sizes, int n_in,
                              void* d_out, int out_size)
{
    const float* x          = (const float*)d_in[0];
    const float* norm_g     = (const float*)d_in[1];
    const float* qkv_w      = (const float*)d_in[2];
    const float* out_w      = (const float*)d_in[3];
    const float* out_b      = (const float*)d_in[4];
    const float* out_norm_g = (const float*)d_in[5];
    float* out = (float*)d_out;

    float *mean, *rstd, *qkv, *ctx, *outpre;
    bf16 *xth, *xtl, *ath, *atl, *wqh, *wql, *woh, *wol;
    cudaGetSymbolAddress((void**)&mean,   g_mean);
    cudaGetSymbolAddress((void**)&rstd,   g_rstd);
    cudaGetSymbolAddress((void**)&xth,    g_xt_h);
    cudaGetSymbolAddress((void**)&xtl,    g_xt_l);
    cudaGetSymbolAddress((void**)&qkv,    g_qkv);
    cudaGetSymbolAddress((void**)&ctx,    g_ctx);
    cudaGetSymbolAddress((void**)&ath,    g_at_h);
    cudaGetSymbolAddress((void**)&atl,    g_at_l);
    cudaGetSymbolAddress((void**)&outpre, g_outpre);
    cudaGetSymbolAddress((void**)&wqh,    g_wq_h);
    cudaGetSymbolAddress((void**)&wql,    g_wq_l);
    cudaGetSymbolAddress((void**)&woh,    g_wo_h);
    cudaGetSymbolAddress((void**)&wol,    g_wo_l);

    cudaFuncSetAttribute(gemm_mma, cudaFuncAttributeMaxDynamicSharedMemorySize,
                         GEMM_SMEM);

    // 1. LN stats + normalize-transpose-split (x -> xt hi/lo, channel-last)
    ln_stats_kernel<<<BATCH * NPOS / 256, 256>>>(x, mean, rstd);
    norm_transpose_kernel<<<dim3(NPOS / 64, CDIM / 64, BATCH), 256>>>(
        x, norm_g, mean, rstd, xth, xtl);

    // 2. weight splits
    split_bf16_kernel<<<(O3 * CDIM) / 256, 256>>>(qkv_w, wqh, wql, O3 * CDIM);
    split_bf16_kernel<<<(HID * CDIM) / 256, 256>>>(out_w, woh, wol, HID * CDIM);

    // 3. qkv GEMM (tensor cores, cp.async pipelined)
    gemm_mma<<<dim3(NPOS / 128, O3 / 128, BATCH), 256, GEMM_SMEM>>>(
        wqh, wql, xth, xtl, qkv, nullptr, O3);

    // 4. softmaxes
    softmax_q_kernel<<<BATCH * HEADS * NPOS / 256, 256>>>(qkv);
    softmax_k_kernel<<<BATCH * HEADS * DH, 256>>>(qkv);

    // 5. context = k @ v^T
    int ctx_n = BATCH * HEADS * DH * DH;
    zero_kernel<<<(ctx_n + 255) / 256, 256>>>(ctx, ctx_n);
    context_kernel<<<dim3(BATCH * HEADS, NSPLIT), 256>>>(qkv, ctx);

    // 6. attn out -> channel-last bf16 hi/lo
    attnout_kernel<<<dim3(NPOS / 128, BATCH * HEADS), 128>>>(qkv, ctx, ath, atl);

    // 7. out projection (tensor cores) + bias -> outpre (channel-major)
    gemm_mma<<<dim3(NPOS / 128, HID / 128, BATCH), 256, GEMM_SMEM>>>(
        woh, wol, ath, atl, outpre, out_b, HID);

    // 8. final channel LN -> d_out
    chan_ln_kernel<<<BATCH * NPOS / 256, 256>>>(outpre, out_norm_g, out);
}

// round 5
// speedup vs baseline: 1.6691x; 1.6691x over previous
#include <cuda_runtime.h>
#include <cuda_bf16.h>
#include <math_constants.h>
#include <cstdint>

#define BATCH 16
#define CDIM  512
#define NPOS  4096      // 64*64
#define O3    1536      // 3*HID
#define HID   512
#define HEADS 8
#define DH    64
#define EPSV  1e-5f
#define QSCALE 0.125f   // DH^-0.5

typedef __nv_bfloat16 bf16;

// ---------------- scratch (device globals; no allocations allowed) ---------
__device__ float g_mean [BATCH * NPOS];
__device__ float g_rstd [BATCH * NPOS];
__device__ bf16  g_xt_h [(size_t)BATCH * NPOS * CDIM];   // x normalized, channel-last, hi
__device__ bf16  g_xt_l [(size_t)BATCH * NPOS * CDIM];   // lo
__device__ float g_qkv  [(size_t)BATCH * O3   * NPOS];   // channel-major
__device__ float g_ctx  [BATCH * HEADS * DH * DH];
__device__ float g_kmx  [BATCH * HEADS * DH];            // k row max
__device__ float g_krz  [BATCH * HEADS * DH];            // k row 1/sum
__device__ bf16  g_at_h [(size_t)BATCH * NPOS * HID];    // attn out, channel-last, hi
__device__ bf16  g_at_l [(size_t)BATCH * NPOS * HID];
__device__ float g_outpre[(size_t)BATCH * CDIM * NPOS];  // pre-final-LN, channel-major
__device__ bf16  g_wq_h [O3  * CDIM];
__device__ bf16  g_wq_l [O3  * CDIM];
__device__ bf16  g_wo_h [HID * CDIM];
__device__ bf16  g_wo_l [HID * CDIM];

// ======================= mma.sync / cp.async helpers (sm_80+) ==============
__device__ __forceinline__ uint32_t smem_to_u32(const void* p) {
    uint32_t a;
    asm("{ .reg .u64 t; cvta.to.shared.u64 t, %1; cvt.u32.u64 %0, t; }"
        : "=r"(a) : "l"(p));
    return a;
}
__device__ __forceinline__ void ldsm_x4(uint32_t& r0, uint32_t& r1,
                                        uint32_t& r2, uint32_t& r3, uint32_t addr) {
    asm volatile("ldmatrix.sync.aligned.m8n8.x4.shared.b16 {%0,%1,%2,%3}, [%4];"
        : "=r"(r0), "=r"(r1), "=r"(r2), "=r"(r3) : "r"(addr));
}
__device__ __forceinline__ void mma16816(float* d, const uint32_t* a,
                                         uint32_t b0, uint32_t b1) {
    asm volatile(
        "mma.sync.aligned.m16n8k16.row.col.f32.bf16.bf16.f32 "
        "{%0,%1,%2,%3},{%4,%5,%6,%7},{%8,%9},{%0,%1,%2,%3};"
        : "+f"(d[0]), "+f"(d[1]), "+f"(d[2]), "+f"(d[3])
        : "r"(a[0]), "r"(a[1]), "r"(a[2]), "r"(a[3]), "r"(b0), "r"(b1));
}
__device__ __forceinline__ void cp_async16(uint32_t saddr, const void* gaddr) {
    asm volatile("cp.async.ca.shared.global [%0], [%1], 16;"
        :: "r"(saddr), "l"(gaddr));
}
#define CP_COMMIT()  asm volatile("cp.async.commit_group;" ::: "memory")
#define CP_WAIT(N)   asm volatile("cp.async.wait_group %0;" :: "n"(N) : "memory")

// ======================= split-bf16 tensor-core GEMM =======================
// Round-3 structure (KC=64, full 128B row segments, synchronous), cp.async loads.
// C[b, bm+r, bn+c] = sum_k A[bm+r, k] * B[b, bn+c, k]  (+ bias[bm+r])
#define KC  64
#define LDT 72          // KC + 8 pad (bf16 units); row stride 144 B
#define TILE_B16 (128 * LDT)            // 9216 bf16 = 18432 B per operand tile
#define GEMM_SMEM (4 * TILE_B16 * 2)    // 73728 B

__global__ __launch_bounds__(256, 2) void gemm_mma(
    const bf16* __restrict__ Ah, const bf16* __restrict__ Al,
    const bf16* __restrict__ Bh, const bf16* __restrict__ Bl,
    float* __restrict__ C, const float* __restrict__ bias, int M_total)
{
    extern __shared__ bf16 sm[];
    uint32_t sbase = smem_to_u32(sm);
    uint32_t uAh = sbase;
    uint32_t uAl = sbase + TILE_B16 * 2;
    uint32_t uBh = sbase + 2 * TILE_B16 * 2;
    uint32_t uBl = sbase + 3 * TILE_B16 * 2;

    int tid = threadIdx.x, wid = tid >> 5, lane = tid & 31;
    int b = blockIdx.z, bm = blockIdx.y * 128, bn = blockIdx.x * 128;
    int warp_m = (wid & 3) * 32;        // 4 warps along M
    int warp_n = (wid >> 2) * 64;       // 2 warps along N

    // global pointers in uint4 units (8 bf16); row pitch = 512/8 = 64
    const uint4* gAh = (const uint4*)Ah + (size_t)bm * 64;
    const uint4* gAl = (const uint4*)Al + (size_t)bm * 64;
    const uint4* gBh = (const uint4*)Bh + ((size_t)b * NPOS + bn) * 64;
    const uint4* gBl = (const uint4*)Bl + ((size_t)b * NPOS + bn) * 64;

    float acc[2][8][4];
    #pragma unroll
    for (int mt = 0; mt < 2; mt++)
        #pragma unroll
        for (int nt = 0; nt < 8; nt++)
            #pragma unroll
            for (int f = 0; f < 4; f++) acc[mt][nt][f] = 0.f;

    for (int kc = 0; kc < 8; kc++) {
        // 1024 uint4 per operand tile; 4 per thread per matrix
        #pragma unroll
        for (int l = 0; l < 4; l++) {
            int i = l * 256 + tid;
            int row = i >> 3, c8 = i & 7;
            size_t go = (size_t)row * 64 + kc * 8 + c8;
            uint32_t so = (uint32_t)(row * LDT + c8 * 8) * 2;
            cp_async16(uAh + so, gAh + go);
            cp_async16(uAl + so, gAl + go);
            cp_async16(uBh + so, gBh + go);
            cp_async16(uBl + so, gBl + go);
        }
        CP_COMMIT();
        CP_WAIT(0);
        __syncthreads();

        #pragma unroll
        for (int kk = 0; kk < 4; kk++) {
            uint32_t ah[2][4], al[2][4];
            #pragma unroll
            for (int mt = 0; mt < 2; mt++) {
                uint32_t off = 2 * (uint32_t)((warp_m + mt * 16 + (lane & 15)) * LDT
                                              + kk * 16 + (lane >> 4) * 8);
                ldsm_x4(ah[mt][0], ah[mt][1], ah[mt][2], ah[mt][3], uAh + off);
                ldsm_x4(al[mt][0], al[mt][1], al[mt][2], al[mt][3], uAl + off);
            }
            #pragma unroll
            for (int nt2 = 0; nt2 < 4; nt2++) {
                uint32_t off = 2 * (uint32_t)((warp_n + nt2 * 16 + (lane & 15)) * LDT
                                              + kk * 16 + (lane >> 4) * 8);
                uint32_t bh0, bh1, bh2, bh3, bl0, bl1, bl2, bl3;
                ldsm_x4(bh0, bh1, bh2, bh3, uBh + off);
                ldsm_x4(bl0, bl1, bl2, bl3, uBl + off);
                #pragma unroll
                for (int mt = 0; mt < 2; mt++) {
                    mma16816(acc[mt][nt2 * 2 + 0], ah[mt], bh0, bh2);
                    mma16816(acc[mt][nt2 * 2 + 1], ah[mt], bh1, bh3);
                    mma16816(acc[mt][nt2 * 2 + 0], ah[mt], bl0, bl2);
                    mma16816(acc[mt][nt2 * 2 + 1], ah[mt], bl1, bl3);
                    mma16816(acc[mt][nt2 * 2 + 0], al[mt], bh0, bh2);
                    mma16816(acc[mt][nt2 * 2 + 1], al[mt], bh1, bh3);
                }
            }
        }
        __syncthreads();
    }

    // writeout: c-frag rows r, r+8; cols 2*(lane%4), +1  -> float2 stores
    #pragma unroll
    for (int mt = 0; mt < 2; mt++) {
        int r0 = bm + warp_m + mt * 16 + (lane >> 2);
        float bb0 = bias ? bias[r0] : 0.f;
        float bb8 = bias ? bias[r0 + 8] : 0.f;
        #pragma unroll
        for (int nt = 0; nt < 8; nt++) {
            int col = bn + warp_n + nt * 8 + 2 * (lane & 3);
            float2 v0 = make_float2(acc[mt][nt][0] + bb0, acc[mt][nt][1] + bb0);
            float2 v1 = make_float2(acc[mt][nt][2] + bb8, acc[mt][nt][3] + bb8);
            *(float2*)&C[((size_t)b * M_total + r0    ) * NPOS + col] = v0;
            *(float2*)&C[((size_t)b * M_total + r0 + 8) * NPOS + col] = v1;
        }
    }
}

// ---------------- LN stats: mean/rstd over C per (b,p) ---------------------
__global__ __launch_bounds__(256) void ln_stats_kernel(
    const float* __restrict__ in, float* __restrict__ mean, float* __restrict__ rstd)
{
    int gid = blockIdx.x * 256 + threadIdx.x;
    int b = gid >> 12, p = gid & (NPOS - 1);
    const float* ip = in + (size_t)b * CDIM * NPOS + p;
    float s = 0.f, s2 = 0.f;
    #pragma unroll 8
    for (int c = 0; c < CDIM; c++) {
        float v = ip[(size_t)c * NPOS];
        s += v; s2 += v * v;
    }
    float m = s * (1.f / CDIM);
    float var = s2 * (1.f / CDIM) - m * m;
    mean[gid] = m;
    rstd[gid] = rsqrtf(var + EPSV);
}

// ---------------- normalize + transpose to channel-last, split bf16 --------
__global__ __launch_bounds__(256) void norm_transpose_kernel(
    const float* __restrict__ x, const float* __restrict__ g,
    const float* __restrict__ mean, const float* __restrict__ rstd,
    bf16* __restrict__ xh, bf16* __restrict__ xl)
{
    __shared__ float t[64][65];
    int b = blockIdx.z, c0 = blockIdx.y * 64, p0 = blockIdx.x * 64;
    int tid = threadIdx.x;
    #pragma unroll
    for (int l = 0; l < 16; l++) {
        int i = l * 256 + tid;
        int c = i >> 6, p = i & 63;
        float v = x[((size_t)b * CDIM + c0 + c) * NPOS + p0 + p];
        int sp = b * NPOS + p0 + p;
        t[p][c] = (v - mean[sp]) * rstd[sp] * g[c0 + c];
    }
    __syncthreads();
    #pragma unroll
    for (int l = 0; l < 16; l++) {
        int i = l * 256 + tid;
        int p = i >> 6, c = i & 63;
        float v = t[p][c];
        bf16 h = __float2bfloat16(v);
        bf16 lo = __float2bfloat16(v - __bfloat162float(h));
        size_t o = ((size_t)b * NPOS + p0 + p) * CDIM + c0 + c;
        xh[o] = h; xl[o] = lo;
    }
}

// ---------------- fp32 -> bf16 hi/lo split (weights) -----------------------
__global__ __launch_bounds__(256) void split_bf16_kernel(
    const float* __restrict__ w, bf16* __restrict__ h, bf16* __restrict__ l, int n)
{
    int i = blockIdx.x * 256 + threadIdx.x;
    if (i < n) {
        float v = w[i];
        bf16 hi = __float2bfloat16(v);
        h[i] = hi;
        l[i] = __float2bfloat16(v - __bfloat162float(hi));
    }
}

// ---------------- warp reductions ------------------------------------------
__device__ __forceinline__ float warp_max(float v) {
    #pragma unroll
    for (int o = 16; o > 0; o >>= 1) v = fmaxf(v, __shfl_xor_sync(0xffffffffu, v, o));
    return v;
}
__device__ __forceinline__ float warp_sum(float v) {
    #pragma unroll
    for (int o = 16; o > 0; o >>= 1) v += __shfl_xor_sync(0xffffffffu, v, o);
    return v;
}

// ---------------- k row stats: max + 1/sum(exp) over n ---------------------
__global__ __launch_bounds__(256) void kstats_kernel(
    const float* __restrict__ qkv, float* __restrict__ kmx, float* __restrict__ krz)
{
    __shared__ float red[8];
    int row = blockIdx.x;                  // BATCH*HEADS*DH rows
    int i = row & (DH - 1);
    int m = (row >> 6) & (HEADS - 1);
    int b = row >> 9;
    const float* base = qkv + (size_t)b * O3 * NPOS + (size_t)(HID + m * DH + i) * NPOS;
    int t = threadIdx.x;
    int lane = t & 31, wid = t >> 5;

    float v[16];
    float mx = -CUDART_INF_F;
    #pragma unroll
    for (int u = 0; u < 16; u++) {
        v[u] = base[u * 256 + t];
        mx = fmaxf(mx, v[u]);
    }
    mx = warp_max(mx);
    if (lane == 0) red[wid] = mx;
    __syncthreads();
    mx = warp_max((lane < 8) ? red[lane] : -CUDART_INF_F);
    mx = __shfl_sync(0xffffffffu, mx, 0);

    float s = 0.f;
    #pragma unroll
    for (int u = 0; u < 16; u++) s += __expf(v[u] - mx);
    s = warp_sum(s);
    __syncthreads();
    if (lane == 0) red[wid] = s;
    __syncthreads();
    s = warp_sum((lane < 8) ? red[lane] : 0.f);
    s = __shfl_sync(0xffffffffu, s, 0);

    if (t == 0) { kmx[row] = mx; krz[row] = 1.f / s; }
}

// ---------------- zero ------------------------------------------------------
__global__ __launch_bounds__(256) void zero_kernel(float* __restrict__ p, int n)
{
    int i = blockIdx.x * 256 + threadIdx.x;
    if (i < n) p[i] = 0.f;
}

// -------- context[b,m,i,j] = (1/Z_i) sum_n exp(k[i,n]-mx_i) * v[j,n] -------
#define NSPLIT 4
__global__ __launch_bounds__(256) void context_kernel(
    const float* __restrict__ qkv, const float* __restrict__ kmx,
    const float* __restrict__ krz, float* __restrict__ ctx)
{
    __shared__ float Ks[64][65];
    __shared__ float Vs[64][65];
    int bm = blockIdx.x;
    int m = bm & (HEADS - 1);
    int b = bm >> 3;
    const float* kbase = qkv + (size_t)b * O3 * NPOS + (size_t)(HID     + m * DH) * NPOS;
    const float* vbase = qkv + (size_t)b * O3 * NPOS + (size_t)(2 * HID + m * DH) * NPOS;
    int tid = threadIdx.x;
    int ti = tid & 15, tj = tid >> 4;

    float acc[4][4];
    #pragma unroll
    for (int a = 0; a < 4; a++)
        #pragma unroll
        for (int c = 0; c < 4; c++) acc[a][c] = 0.f;

    int nsplit = NPOS / NSPLIT;
    int nstart = blockIdx.y * nsplit;
    for (int nc = 0; nc < nsplit; nc += 64) {
        int nb = nstart + nc;
        #pragma unroll
        for (int l = 0; l < 16; l++) {
            int idx = l * 256 + tid;
            int i = idx >> 6, nn = idx & 63;
            Ks[nn][i] = __expf(kbase[(size_t)i * NPOS + nb + nn] - kmx[bm * DH + i]);
            Vs[nn][i] = vbase[(size_t)i * NPOS + nb + nn];
        }
        __syncthreads();
        #pragma unroll 8
        for (int nn = 0; nn < 64; nn++) {
            float ka[4], vb[4];
            #pragma unroll
            for (int a = 0; a < 4; a++) ka[a] = Ks[nn][ti * 4 + a];
            #pragma unroll
            for (int c = 0; c < 4; c++) vb[c] = Vs[nn][tj * 4 + c];
            #pragma unroll
            for (int a = 0; a < 4; a++)
                #pragma unroll
                for (int c = 0; c < 4; c++) acc[a][c] += ka[a] * vb[c];
        }
        __syncthreads();
    }
    #pragma unroll
    for (int a = 0; a < 4; a++) {
        float rz = krz[bm * DH + ti * 4 + a];
        #pragma unroll
        for (int c = 0; c < 4; c++)
            atomicAdd(&ctx[(size_t)bm * DH * DH + (ti * 4 + a) * DH + (tj * 4 + c)],
                      acc[a][c] * rz);
    }
}

// -------- attn_out -> channel-last bf16 hi/lo, with INLINE q softmax -------
// attn_t[b, n, m*64+j] = sum_i ctx[b,m,i,j] * softmax_i(q[b,m,i,n]) * scale
__global__ __launch_bounds__(128) void attnout_kernel(
    const float* __restrict__ qkv, const float* __restrict__ ctx,
    bf16* __restrict__ ath, bf16* __restrict__ atl)
{
    __shared__ float cs[DH][DH];        // 16 KB
    __shared__ float stage[128][64];    // 32 KB (rotated to dodge bank conflicts)
    int bm = blockIdx.y;
    int m = bm & (HEADS - 1);
    int b = bm >> 3;
    const float* qbase = qkv + (size_t)b * O3 * NPOS + (size_t)(m * DH) * NPOS;
    int tid = threadIdx.x;

    #pragma unroll
    for (int l = 0; l < 32; l++)
        ((float*)cs)[l * 128 + tid] = ctx[(size_t)bm * DH * DH + l * 128 + tid];
    __syncthreads();

    int n0 = blockIdx.x * 128;
    int n = n0 + tid;

    // inline softmax over head-dim of q column
    float v[DH];
    float mx = -CUDART_INF_F;
    #pragma unroll
    for (int i = 0; i < DH; i++) {
        v[i] = qbase[(size_t)i * NPOS + n];
        mx = fmaxf(mx, v[i]);
    }
    float s = 0.f;
    #pragma unroll
    for (int i = 0; i < DH; i++) { v[i] = __expf(v[i] - mx); s += v[i]; }
    float r = QSCALE / s;

    float accj[DH];
    #pragma unroll
    for (int j = 0; j < DH; j++) accj[j] = 0.f;

    #pragma unroll 2
    for (int i = 0; i < DH; i++) {
        float qv = v[i];
        const float4* rowp = (const float4*)cs[i];
        #pragma unroll
        for (int j4 = 0; j4 < 16; j4++) {
            float4 c4 = rowp[j4];
            accj[j4 * 4 + 0] += c4.x * qv;
            accj[j4 * 4 + 1] += c4.y * qv;
            accj[j4 * 4 + 2] += c4.z * qv;
            accj[j4 * 4 + 3] += c4.w * qv;
        }
    }
    // rotated store (apply softmax denominator * scale here)
    #pragma unroll
    for (int j = 0; j < DH; j++) stage[tid][(j + tid) & 63] = accj[j] * r;
    __syncthreads();

    // coalesced channel-last write with hi/lo split
    #pragma unroll
    for (int l = 0; l < 64; l++) {
        int idx = l * 128 + tid;
        int p = idx >> 6, j = idx & 63;
        float val = stage[p][(j + p) & 63];
        bf16 h = __float2bfloat16(val);
        bf16 lo = __float2bfloat16(val - __bfloat162float(h));
        size_t o = ((size_t)b * NPOS + n0 + p) * HID + m * DH + j;
        ath[o] = h; atl[o] = lo;
    }
}

// ---------------- final channel layernorm (channel-major, 2-pass) ----------
__global__ __launch_bounds__(256) void chan_ln_kernel(
    const float* __restrict__ in, const float* __restrict__ g,
    float* __restrict__ out)
{
    int gid = blockIdx.x * 256 + threadIdx.x;
    int b = gid >> 12;
    int p = gid & (NPOS - 1);
    const float* ip = in  + (size_t)b * CDIM * NPOS + p;
    float*       op = out + (size_t)b * CDIM * NPOS + p;

    float s = 0.f, s2 = 0.f;
    #pragma unroll 8
    for (int c = 0; c < CDIM; c++) {
        float v = ip[(size_t)c * NPOS];
        s += v; s2 += v * v;
    }
    float mean = s * (1.f / CDIM);
    float var = s2 * (1.f / CDIM) - mean * mean;
    float rstd = rsqrtf(var + EPSV);

    #pragma unroll 8
    for (int c = 0; c < CDIM; c++) {
        float v = ip[(size_t)c * NPOS];
        op[(size_t)c * NPOS] = (v - mean) * rstd * g[c];
    }
}

// ---------------- launch ---------------------------------------------------
extern "C" void kernel_launch(void* const* d_in, const int* in_sizes, int n_in,
                              void* d_out, int out_size)
{
    const float* x          = (const float*)d_in[0];
    const float* norm_g     = (const float*)d_in[1];
    const float* qkv_w      = (const float*)d_in[2];
    const float* out_w      = (const float*)d_in[3];
    const float* out_b      = (const float*)d_in[4];
    const float* out_norm_g = (const float*)d_in[5];
    float* out = (float*)d_out;

    float *mean, *rstd, *qkv, *ctx, *outpre, *kmx, *krz;
    bf16 *xth, *xtl, *ath, *atl, *wqh, *wql, *woh, *wol;
    cudaGetSymbolAddress((void**)&mean,   g_mean);
    cudaGetSymbolAddress((void**)&rstd,   g_rstd);
    cudaGetSymbolAddress((void**)&xth,    g_xt_h);
    cudaGetSymbolAddress((void**)&xtl,    g_xt_l);
    cudaGetSymbolAddress((void**)&qkv,    g_qkv);
    cudaGetSymbolAddress((void**)&ctx,    g_ctx);
    cudaGetSymbolAddress((void**)&kmx,    g_kmx);
    cudaGetSymbolAddress((void**)&krz,    g_krz);
    cudaGetSymbolAddress((void**)&ath,    g_at_h);
    cudaGetSymbolAddress((void**)&atl,    g_at_l);
    cudaGetSymbolAddress((void**)&outpre, g_outpre);
    cudaGetSymbolAddress((void**)&wqh,    g_wq_h);
    cudaGetSymbolAddress((void**)&wql,    g_wq_l);
    cudaGetSymbolAddress((void**)&woh,    g_wo_h);
    cudaGetSymbolAddress((void**)&wol,    g_wo_l);

    cudaFuncSetAttribute(gemm_mma, cudaFuncAttributeMaxDynamicSharedMemorySize,
                         GEMM_SMEM);

    // 1. LN stats + normalize-transpose-split (x -> xt hi/lo, channel-last)
    ln_stats_kernel<<<BATCH * NPOS / 256, 256>>>(x, mean, rstd);
    norm_transpose_kernel<<<dim3(NPOS / 64, CDIM / 64, BATCH), 256>>>(
        x, norm_g, mean, rstd, xth, xtl);

    // 2. weight splits
    split_bf16_kernel<<<(O3 * CDIM) / 256, 256>>>(qkv_w, wqh, wql, O3 * CDIM);
    split_bf16_kernel<<<(HID * CDIM) / 256, 256>>>(out_w, woh, wol, HID * CDIM);

    // 3. qkv GEMM (tensor cores)
    gemm_mma<<<dim3(NPOS / 128, O3 / 128, BATCH), 256, GEMM_SMEM>>>(
        wqh, wql, xth, xtl, qkv, nullptr, O3);

    // 4. k row stats (softmax_k folded into context)
    kstats_kernel<<<BATCH * HEADS * DH, 256>>>(qkv, kmx, krz);

    // 5. context = softmax(k) @ v^T  (exp applied inline, 1/Z in epilogue)
    int ctx_n = BATCH * HEADS * DH * DH;
    zero_kernel<<<(ctx_n + 255) / 256, 256>>>(ctx, ctx_n);
    context_kernel<<<dim3(BATCH * HEADS, NSPLIT), 256>>>(qkv, kmx, krz, ctx);

    // 6. attn out (inline q softmax) -> channel-last bf16 hi/lo
    attnout_kernel<<<dim3(NPOS / 128, BATCH * HEADS), 128>>>(qkv, ctx, ath, atl);

    // 7. out projection (tensor cores) + bias -> outpre (channel-major)
    gemm_mma<<<dim3(NPOS / 128, HID / 128, BATCH), 256, GEMM_SMEM>>>(
        woh, wol, ath, atl, outpre, out_b, HID);

    // 8. final channel LN -> d_out
    chan_ln_kernel<<<BATCH * NPOS / 256, 256>>>(outpre, out_norm_g, out);
}

// round 6
// speedup vs baseline: 1.9875x; 1.1908x over previous
#include <cuda_runtime.h>
#include <cuda_fp16.h>
#include <math_constants.h>
#include <cstdint>

#define BATCH 16
#define CDIM  512
#define NPOS  4096      // 64*64
#define O3    1536      // 3*HID
#define HID   512
#define HEADS 8
#define DH    64
#define EPSV  1e-5f
#define QSCALE 0.125f   // DH^-0.5

typedef __half h16;

// ---------------- scratch (device globals; no allocations allowed) ---------
__device__ float g_mean [BATCH * NPOS];
__device__ float g_rstd [BATCH * NPOS];
__device__ h16   g_xt   [(size_t)BATCH * NPOS * CDIM];   // x normalized, channel-last fp16
__device__ float g_qkv  [(size_t)BATCH * O3   * NPOS];   // channel-major
__device__ float g_ctx  [BATCH * HEADS * DH * DH];
__device__ float g_kmx  [BATCH * HEADS * DH];            // k row max
__device__ float g_krz  [BATCH * HEADS * DH];            // k row 1/sum
__device__ h16   g_at   [(size_t)BATCH * NPOS * HID];    // attn out, channel-last fp16
__device__ float g_outpre[(size_t)BATCH * CDIM * NPOS];  // pre-final-LN, channel-major
__device__ h16   g_wq_h [O3  * CDIM];
__device__ h16   g_wq_l [O3  * CDIM];
__device__ h16   g_wo_h [HID * CDIM];
__device__ h16   g_wo_l [HID * CDIM];

// ======================= mma.sync / cp.async helpers (sm_80+) ==============
__device__ __forceinline__ uint32_t smem_to_u32(const void* p) {
    uint32_t a;
    asm("{ .reg .u64 t; cvta.to.shared.u64 t, %1; cvt.u32.u64 %0, t; }"
        : "=r"(a) : "l"(p));
    return a;
}
__device__ __forceinline__ void ldsm_x4(uint32_t& r0, uint32_t& r1,
                                        uint32_t& r2, uint32_t& r3, uint32_t addr) {
    asm volatile("ldmatrix.sync.aligned.m8n8.x4.shared.b16 {%0,%1,%2,%3}, [%4];"
        : "=r"(r0), "=r"(r1), "=r"(r2), "=r"(r3) : "r"(addr));
}
__device__ __forceinline__ void mma16816(float* d, const uint32_t* a,
                                         uint32_t b0, uint32_t b1) {
    asm volatile(
        "mma.sync.aligned.m16n8k16.row.col.f32.f16.f16.f32 "
        "{%0,%1,%2,%3},{%4,%5,%6,%7},{%8,%9},{%0,%1,%2,%3};"
        : "+f"(d[0]), "+f"(d[1]), "+f"(d[2]), "+f"(d[3])
        : "r"(a[0]), "r"(a[1]), "r"(a[2]), "r"(a[3]), "r"(b0), "r"(b1));
}
__device__ __forceinline__ void cp_async16(uint32_t saddr, const void* gaddr) {
    asm volatile("cp.async.ca.shared.global [%0], [%1], 16;"
        :: "r"(saddr), "l"(gaddr));
}
#define CP_COMMIT()  asm volatile("cp.async.commit_group;" ::: "memory")
#define CP_WAIT(N)   asm volatile("cp.async.wait_group %0;" :: "n"(N) : "memory")

// ======================= 2-product split-fp16 tensor-core GEMM =============
// C[b, bm+r, bn+c] = sum_k (Wh+Wl)[bm+r, k] * X[b, bn+c, k]  (+ bias[bm+r])
// W: [M_total, 512] fp16 hi/lo K-contiguous. X: [b, 4096, 512] fp16.
#define KC  64
#define LDT 72                              // KC + 8 pad; row stride 144 B
#define TILE_BYTES (128 * LDT * 2)          // 18432 B per tile
#define STAGE_BYTES (3 * TILE_BYTES)        // Wh, Wl, X  -> 55296 B
#define GEMM_SMEM  (2 * STAGE_BYTES)        // 110592 B (2 stages)

__global__ __launch_bounds__(256, 2) void gemm_mma(
    const h16* __restrict__ Wh, const h16* __restrict__ Wl,
    const h16* __restrict__ X,
    float* __restrict__ C, const float* __restrict__ bias, int M_total)
{
    extern __shared__ char sm[];
    uint32_t sbase = smem_to_u32(sm);

    int tid = threadIdx.x, wid = tid >> 5, lane = tid & 31;
    int b = blockIdx.z, bm = blockIdx.y * 128, bn = blockIdx.x * 128;
    int warp_m = (wid & 3) * 32;        // 4 warps along M
    int warp_n = (wid >> 2) * 64;       // 2 warps along N

    // global pointers in uint4 units (8 fp16); row pitch = 512/8 = 64
    const uint4* gWh = (const uint4*)Wh + (size_t)bm * 64;
    const uint4* gWl = (const uint4*)Wl + (size_t)bm * 64;
    const uint4* gX  = (const uint4*)X  + ((size_t)b * NPOS + bn) * 64;

    float acc[2][8][4];
    #pragma unroll
    for (int mt = 0; mt < 2; mt++)
        #pragma unroll
        for (int nt = 0; nt < 8; nt++)
            #pragma unroll
            for (int f = 0; f < 4; f++) acc[mt][nt][f] = 0.f;

    auto load_stage = [&](int s, int kc) {
        uint32_t ub = sbase + (uint32_t)s * STAGE_BYTES;
        #pragma unroll
        for (int l = 0; l < 4; l++) {
            int i = l * 256 + tid;
            int row = i >> 3, c8 = i & 7;
            size_t go = (size_t)row * 64 + kc * 8 + c8;
            uint32_t so = ub + (uint32_t)(row * LDT + c8 * 8) * 2;
            cp_async16(so,                  gWh + go);
            cp_async16(so + TILE_BYTES,     gWl + go);
            cp_async16(so + 2 * TILE_BYTES, gX  + go);
        }
    };

    load_stage(0, 0);
    CP_COMMIT();

    for (int kc = 0; kc < 8; kc++) {
        if (kc + 1 < 8) {
            load_stage((kc + 1) & 1, kc + 1);
            CP_COMMIT();
            CP_WAIT(1);
        } else {
            CP_WAIT(0);
        }
        __syncthreads();

        uint32_t ub  = sbase + (uint32_t)(kc & 1) * STAGE_BYTES;
        uint32_t uWh = ub;
        uint32_t uWl = ub + TILE_BYTES;
        uint32_t uX  = ub + 2 * TILE_BYTES;

        #pragma unroll
        for (int kk = 0; kk < 4; kk++) {
            uint32_t ah[2][4], al[2][4];
            #pragma unroll
            for (int mt = 0; mt < 2; mt++) {
                uint32_t off = 2 * (uint32_t)((warp_m + mt * 16 + (lane & 15)) * LDT
                                              + kk * 16 + (lane >> 4) * 8);
                ldsm_x4(ah[mt][0], ah[mt][1], ah[mt][2], ah[mt][3], uWh + off);
                ldsm_x4(al[mt][0], al[mt][1], al[mt][2], al[mt][3], uWl + off);
            }
            #pragma unroll
            for (int nt2 = 0; nt2 < 4; nt2++) {
                uint32_t off = 2 * (uint32_t)((warp_n + nt2 * 16 + (lane & 15)) * LDT
                                              + kk * 16 + (lane >> 4) * 8);
                uint32_t b0, b1, b2, b3;
                ldsm_x4(b0, b1, b2, b3, uX + off);
                #pragma unroll
                for (int mt = 0; mt < 2; mt++) {
                    mma16816(acc[mt][nt2 * 2 + 0], ah[mt], b0, b2);
                    mma16816(acc[mt][nt2 * 2 + 1], ah[mt], b1, b3);
                    mma16816(acc[mt][nt2 * 2 + 0], al[mt], b0, b2);
                    mma16816(acc[mt][nt2 * 2 + 1], al[mt], b1, b3);
                }
            }
        }
        __syncthreads();   // compute done before next prefetch overwrites
    }

    // writeout: c-frag rows r, r+8; cols 2*(lane%4), +1  -> float2 stores
    #pragma unroll
    for (int mt = 0; mt < 2; mt++) {
        int r0 = bm + warp_m + mt * 16 + (lane >> 2);
        float bb0 = bias ? bias[r0] : 0.f;
        float bb8 = bias ? bias[r0 + 8] : 0.f;
        #pragma unroll
        for (int nt = 0; nt < 8; nt++) {
            int col = bn + warp_n + nt * 8 + 2 * (lane & 3);
            float2 v0 = make_float2(acc[mt][nt][0] + bb0, acc[mt][nt][1] + bb0);
            float2 v1 = make_float2(acc[mt][nt][2] + bb8, acc[mt][nt][3] + bb8);
            *(float2*)&C[((size_t)b * M_total + r0    ) * NPOS + col] = v0;
            *(float2*)&C[((size_t)b * M_total + r0 + 8) * NPOS + col] = v1;
        }
    }
}

// ---------------- LN stats: mean/rstd over C per (b,p) ---------------------
__global__ __launch_bounds__(256) void ln_stats_kernel(
    const float* __restrict__ in, float* __restrict__ mean, float* __restrict__ rstd)
{
    int gid = blockIdx.x * 256 + threadIdx.x;
    int b = gid >> 12, p = gid & (NPOS - 1);
    const float* ip = in + (size_t)b * CDIM * NPOS + p;
    float s = 0.f, s2 = 0.f;
    #pragma unroll 8
    for (int c = 0; c < CDIM; c++) {
        float v = ip[(size_t)c * NPOS];
        s += v; s2 += v * v;
    }
    float m = s * (1.f / CDIM);
    float var = s2 * (1.f / CDIM) - m * m;
    mean[gid] = m;
    rstd[gid] = rsqrtf(var + EPSV);
}

// ---------------- normalize + transpose to channel-last fp16 ---------------
__global__ __launch_bounds__(256) void norm_transpose_kernel(
    const float* __restrict__ x, const float* __restrict__ g,
    const float* __restrict__ mean, const float* __restrict__ rstd,
    h16* __restrict__ xt)
{
    __shared__ float t[64][65];
    int b = blockIdx.z, c0 = blockIdx.y * 64, p0 = blockIdx.x * 64;
    int tid = threadIdx.x;
    #pragma unroll
    for (int l = 0; l < 16; l++) {
        int i = l * 256 + tid;
        int c = i >> 6, p = i & 63;
        float v = x[((size_t)b * CDIM + c0 + c) * NPOS + p0 + p];
        int sp = b * NPOS + p0 + p;
        t[p][c] = (v - mean[sp]) * rstd[sp] * g[c0 + c];
    }
    __syncthreads();
    #pragma unroll
    for (int l = 0; l < 16; l++) {
        int i = l * 256 + tid;
        int p = i >> 6, c = i & 63;
        size_t o = ((size_t)b * NPOS + p0 + p) * CDIM + c0 + c;
        xt[o] = __float2half(t[p][c]);
    }
}

// ---------------- fp32 -> fp16 hi/lo split (weights) -----------------------
__global__ __launch_bounds__(256) void split_fp16_kernel(
    const float* __restrict__ w, h16* __restrict__ h, h16* __restrict__ l, int n)
{
    int i = blockIdx.x * 256 + threadIdx.x;
    if (i < n) {
        float v = w[i];
        h16 hi = __float2half(v);
        h[i] = hi;
        l[i] = __float2half(v - __half2float(hi));
    }
}

// ---------------- warp reductions ------------------------------------------
__device__ __forceinline__ float warp_max(float v) {
    #pragma unroll
    for (int o = 16; o > 0; o >>= 1) v = fmaxf(v, __shfl_xor_sync(0xffffffffu, v, o));
    return v;
}
__device__ __forceinline__ float warp_sum(float v) {
    #pragma unroll
    for (int o = 16; o > 0; o >>= 1) v += __shfl_xor_sync(0xffffffffu, v, o);
    return v;
}

// ---------------- k row stats: max + 1/sum(exp) over n ---------------------
__global__ __launch_bounds__(256) void kstats_kernel(
    const float* __restrict__ qkv, float* __restrict__ kmx, float* __restrict__ krz)
{
    __shared__ float red[8];
    int row = blockIdx.x;                  // BATCH*HEADS*DH rows
    int i = row & (DH - 1);
    int m = (row >> 6) & (HEADS - 1);
    int b = row >> 9;
    const float* base = qkv + (size_t)b * O3 * NPOS + (size_t)(HID + m * DH + i) * NPOS;
    int t = threadIdx.x;
    int lane = t & 31, wid = t >> 5;

    float v[16];
    float mx = -CUDART_INF_F;
    #pragma unroll
    for (int u = 0; u < 16; u++) {
        v[u] = base[u * 256 + t];
        mx = fmaxf(mx, v[u]);
    }
    mx = warp_max(mx);
    if (lane == 0) red[wid] = mx;
    __syncthreads();
    mx = warp_max((lane < 8) ? red[lane] : -CUDART_INF_F);
    mx = __shfl_sync(0xffffffffu, mx, 0);

    float s = 0.f;
    #pragma unroll
    for (int u = 0; u < 16; u++) s += __expf(v[u] - mx);
    s = warp_sum(s);
    __syncthreads();
    if (lane == 0) red[wid] = s;
    __syncthreads();
    s = warp_sum((lane < 8) ? red[lane] : 0.f);
    s = __shfl_sync(0xffffffffu, s, 0);

    if (t == 0) { kmx[row] = mx; krz[row] = 1.f / s; }
}

// ---------------- zero ------------------------------------------------------
__global__ __launch_bounds__(256) void zero_kernel(float* __restrict__ p, int n)
{
    int i = blockIdx.x * 256 + threadIdx.x;
    if (i < n) p[i] = 0.f;
}

// -------- context[b,m,i,j] = (1/Z_i) sum_n exp(k[i,n]-mx_i) * v[j,n] -------
#define NSPLIT 4
__global__ __launch_bounds__(256) void context_kernel(
    const float* __restrict__ qkv, const float* __restrict__ kmx,
    const float* __restrict__ krz, float* __restrict__ ctx)
{
    __shared__ float Ks[64][65];
    __shared__ float Vs[64][65];
    int bm = blockIdx.x;
    int m = bm & (HEADS - 1);
    int b = bm >> 3;
    const float* kbase = qkv + (size_t)b * O3 * NPOS + (size_t)(HID     + m * DH) * NPOS;
    const float* vbase = qkv + (size_t)b * O3 * NPOS + (size_t)(2 * HID + m * DH) * NPOS;
    int tid = threadIdx.x;
    int ti = tid & 15, tj = tid >> 4;

    float acc[4][4];
    #pragma unroll
    for (int a = 0; a < 4; a++)
        #pragma unroll
        for (int c = 0; c < 4; c++) acc[a][c] = 0.f;

    int nsplit = NPOS / NSPLIT;
    int nstart = blockIdx.y * nsplit;
    for (int nc = 0; nc < nsplit; nc += 64) {
        int nb = nstart + nc;
        #pragma unroll
        for (int l = 0; l < 16; l++) {
            int idx = l * 256 + tid;
            int i = idx >> 6, nn = idx & 63;
            Ks[nn][i] = __expf(kbase[(size_t)i * NPOS + nb + nn] - kmx[bm * DH + i]);
            Vs[nn][i] = vbase[(size_t)i * NPOS + nb + nn];
        }
        __syncthreads();
        #pragma unroll 8
        for (int nn = 0; nn < 64; nn++) {
            float ka[4], vb[4];
            #pragma unroll
            for (int a = 0; a < 4; a++) ka[a] = Ks[nn][ti * 4 + a];
            #pragma unroll
            for (int c = 0; c < 4; c++) vb[c] = Vs[nn][tj * 4 + c];
            #pragma unroll
            for (int a = 0; a < 4; a++)
                #pragma unroll
                for (int c = 0; c < 4; c++) acc[a][c] += ka[a] * vb[c];
        }
        __syncthreads();
    }
    #pragma unroll
    for (int a = 0; a < 4; a++) {
        float rz = krz[bm * DH + ti * 4 + a];
        #pragma unroll
        for (int c = 0; c < 4; c++)
            atomicAdd(&ctx[(size_t)bm * DH * DH + (ti * 4 + a) * DH + (tj * 4 + c)],
                      acc[a][c] * rz);
    }
}

// -------- attn_out -> channel-last fp16, with INLINE q softmax -------------
// attn_t[b, n, m*64+j] = sum_i ctx[b,m,i,j] * softmax_i(q[b,m,i,n]) * scale
__global__ __launch_bounds__(128) void attnout_kernel(
    const float* __restrict__ qkv, const float* __restrict__ ctx,
    h16* __restrict__ at)
{
    __shared__ float cs[DH][DH];        // 16 KB
    __shared__ float stage[128][64];    // 32 KB (rotated to dodge bank conflicts)
    int bm = blockIdx.y;
    int m = bm & (HEADS - 1);
    int b = bm >> 3;
    const float* qbase = qkv + (size_t)b * O3 * NPOS + (size_t)(m * DH) * NPOS;
    int tid = threadIdx.x;

    #pragma unroll
    for (int l = 0; l < 32; l++)
        ((float*)cs)[l * 128 + tid] = ctx[(size_t)bm * DH * DH + l * 128 + tid];
    __syncthreads();

    int n0 = blockIdx.x * 128;
    int n = n0 + tid;

    // inline softmax over head-dim of q column
    float v[DH];
    float mx = -CUDART_INF_F;
    #pragma unroll
    for (int i = 0; i < DH; i++) {
        v[i] = qbase[(size_t)i * NPOS + n];
        mx = fmaxf(mx, v[i]);
    }
    float s = 0.f;
    #pragma unroll
    for (int i = 0; i < DH; i++) { v[i] = __expf(v[i] - mx); s += v[i]; }
    float r = QSCALE / s;

    float accj[DH];
    #pragma unroll
    for (int j = 0; j < DH; j++) accj[j] = 0.f;

    #pragma unroll 2
    for (int i = 0; i < DH; i++) {
        float qv = v[i];
        const float4* rowp = (const float4*)cs[i];
        #pragma unroll
        for (int j4 = 0; j4 < 16; j4++) {
            float4 c4 = rowp[j4];
            accj[j4 * 4 + 0] += c4.x * qv;
            accj[j4 * 4 + 1] += c4.y * qv;
            accj[j4 * 4 + 2] += c4.z * qv;
            accj[j4 * 4 + 3] += c4.w * qv;
        }
    }
    // rotated store (apply softmax denominator * scale here)
    #pragma unroll
    for (int j = 0; j < DH; j++) stage[tid][(j + tid) & 63] = accj[j] * r;
    __syncthreads();

    // coalesced channel-last fp16 write
    #pragma unroll
    for (int l = 0; l < 64; l++) {
        int idx = l * 128 + tid;
        int p = idx >> 6, j = idx & 63;
        size_t o = ((size_t)b * NPOS + n0 + p) * HID + m * DH + j;
        at[o] = __float2half(stage[p][(j + p) & 63]);
    }
}

// ---------------- final channel layernorm (channel-major, 2-pass) ----------
__global__ __launch_bounds__(256) void chan_ln_kernel(
    const float* __restrict__ in, const float* __restrict__ g,
    float* __restrict__ out)
{
    int gid = blockIdx.x * 256 + threadIdx.x;
    int b = gid >> 12;
    int p = gid & (NPOS - 1);
    const float* ip = in  + (size_t)b * CDIM * NPOS + p;
    float*       op = out + (size_t)b * CDIM * NPOS + p;

    float s = 0.f, s2 = 0.f;
    #pragma unroll 8
    for (int c = 0; c < CDIM; c++) {
        float v = ip[(size_t)c * NPOS];
        s += v; s2 += v * v;
    }
    float mean = s * (1.f / CDIM);
    float var = s2 * (1.f / CDIM) - mean * mean;
    float rstd = rsqrtf(var + EPSV);

    #pragma unroll 8
    for (int c = 0; c < CDIM; c++) {
        float v = ip[(size_t)c * NPOS];
        op[(size_t)c * NPOS] = (v - mean) * rstd * g[c];
    }
}

// ---------------- launch ---------------------------------------------------
extern "C" void kernel_launch(void* const* d_in, const int* in_sizes, int n_in,
                              void* d_out, int out_size)
{
    const float* x          = (const float*)d_in[0];
    const float* norm_g     = (const float*)d_in[1];
    const float* qkv_w      = (const float*)d_in[2];
    const float* out_w      = (const float*)d_in[3];
    const float* out_b      = (const float*)d_in[4];
    const float* out_norm_g = (const float*)d_in[5];
    float* out = (float*)d_out;

    float *mean, *rstd, *qkv, *ctx, *outpre, *kmx, *krz;
    h16 *xt, *at, *wqh, *wql, *woh, *wol;
    cudaGetSymbolAddress((void**)&mean,   g_mean);
    cudaGetSymbolAddress((void**)&rstd,   g_rstd);
    cudaGetSymbolAddress((void**)&xt,     g_xt);
    cudaGetSymbolAddress((void**)&qkv,    g_qkv);
    cudaGetSymbolAddress((void**)&ctx,    g_ctx);
    cudaGetSymbolAddress((void**)&kmx,    g_kmx);
    cudaGetSymbolAddress((void**)&krz,    g_krz);
    cudaGetSymbolAddress((void**)&at,     g_at);
    cudaGetSymbolAddress((void**)&outpre, g_outpre);
    cudaGetSymbolAddress((void**)&wqh,    g_wq_h);
    cudaGetSymbolAddress((void**)&wql,    g_wq_l);
    cudaGetSymbolAddress((void**)&woh,    g_wo_h);
    cudaGetSymbolAddress((void**)&wol,    g_wo_l);

    cudaFuncSetAttribute(gemm_mma, cudaFuncAttributeMaxDynamicSharedMemorySize,
                         GEMM_SMEM);

    // 1. LN stats + normalize-transpose (x -> xt fp16, channel-last)
    ln_stats_kernel<<<BATCH * NPOS / 256, 256>>>(x, mean, rstd);
    norm_transpose_kernel<<<dim3(NPOS / 64, CDIM / 64, BATCH), 256>>>(
        x, norm_g, mean, rstd, xt);

    // 2. weight splits (fp16 hi/lo)
    split_fp16_kernel<<<(O3 * CDIM) / 256, 256>>>(qkv_w, wqh, wql, O3 * CDIM);
    split_fp16_kernel<<<(HID * CDIM) / 256, 256>>>(out_w, woh, wol, HID * CDIM);

    // 3. qkv GEMM (tensor cores, 2-product split-fp16, double-buffered)
    gemm_mma<<<dim3(NPOS / 128, O3 / 128, BATCH), 256, GEMM_SMEM>>>(
        wqh, wql, xt, qkv, nullptr, O3);

    // 4. k row stats (softmax_k folded into context)
    kstats_kernel<<<BATCH * HEADS * DH, 256>>>(qkv, kmx, krz);

    // 5. context = softmax(k) @ v^T  (exp applied inline, 1/Z in epilogue)
    int ctx_n = BATCH * HEADS * DH * DH;
    zero_kernel<<<(ctx_n + 255) / 256, 256>>>(ctx, ctx_n);
    context_kernel<<<dim3(BATCH * HEADS, NSPLIT), 256>>>(qkv, kmx, krz, ctx);

    // 6. attn out (inline q softmax) -> channel-last fp16
    attnout_kernel<<<dim3(NPOS / 128, BATCH * HEADS), 128>>>(qkv, ctx, at);

    // 7. out projection (tensor cores) + bias -> outpre (channel-major)
    gemm_mma<<<dim3(NPOS / 128, HID / 128, BATCH), 256, GEMM_SMEM>>>(
        woh, wol, at, outpre, out_b, HID);

    // 8. final channel LN -> d_out
    chan_ln_kernel<<<BATCH * NPOS / 256, 256>>>(outpre, out_norm_g, out);
}

// round 7
// speedup vs baseline: 2.7297x; 1.3734x over previous
#include <cuda_runtime.h>
#include <cuda_fp16.h>
#include <math_constants.h>
#include <cstdint>

#define BATCH 16
#define CDIM  512
#define NPOS  4096      // 64*64
#define O3    1536      // 3*HID
#define HID   512
#define HEADS 8
#define DH    64
#define EPSV  1e-5f
#define QSCALE 0.125f   // DH^-0.5

typedef __half h16;

// ---------------- scratch (device globals; no allocations allowed) ---------
__device__ float g_mean [BATCH * NPOS];
__device__ float g_rstd [BATCH * NPOS];
__device__ h16   g_xt   [(size_t)BATCH * NPOS * CDIM];   // x normalized, channel-last fp16
__device__ float g_qkv  [(size_t)BATCH * O3   * NPOS];   // channel-major
__device__ float g_ctx  [BATCH * HEADS * DH * DH];
__device__ float g_kmx  [BATCH * HEADS * DH];            // k row max
__device__ float g_krz  [BATCH * HEADS * DH];            // k row 1/sum
__device__ h16   g_at   [(size_t)BATCH * NPOS * HID];    // attn out, channel-last fp16
__device__ float g_outpre[(size_t)BATCH * CDIM * NPOS];  // pre-final-LN, channel-major
__device__ h16   g_wq   [O3  * CDIM];
__device__ h16   g_wo   [HID * CDIM];

// ======================= mma.sync / cp.async helpers (sm_80+) ==============
__device__ __forceinline__ uint32_t smem_to_u32(const void* p) {
    uint32_t a;
    asm("{ .reg .u64 t; cvta.to.shared.u64 t, %1; cvt.u32.u64 %0, t; }"
        : "=r"(a) : "l"(p));
    return a;
}
__device__ __forceinline__ void ldsm_x4(uint32_t& r0, uint32_t& r1,
                                        uint32_t& r2, uint32_t& r3, uint32_t addr) {
    asm volatile("ldmatrix.sync.aligned.m8n8.x4.shared.b16 {%0,%1,%2,%3}, [%4];"
        : "=r"(r0), "=r"(r1), "=r"(r2), "=r"(r3) : "r"(addr));
}
__device__ __forceinline__ void mma16816(float* d, const uint32_t* a,
                                         uint32_t b0, uint32_t b1) {
    asm volatile(
        "mma.sync.aligned.m16n8k16.row.col.f32.f16.f16.f32 "
        "{%0,%1,%2,%3},{%4,%5,%6,%7},{%8,%9},{%0,%1,%2,%3};"
        : "+f"(d[0]), "+f"(d[1]), "+f"(d[2]), "+f"(d[3])
        : "r"(a[0]), "r"(a[1]), "r"(a[2]), "r"(a[3]), "r"(b0), "r"(b1));
}
__device__ __forceinline__ void cp_async16(uint32_t saddr, const void* gaddr) {
    asm volatile("cp.async.ca.shared.global [%0], [%1], 16;"
        :: "r"(saddr), "l"(gaddr));
}
#define CP_COMMIT()  asm volatile("cp.async.commit_group;" ::: "memory")
#define CP_WAIT(N)   asm volatile("cp.async.wait_group %0;" :: "n"(N) : "memory")

// ======================= single-product fp16 tensor-core GEMM ==============
// C[b, bm+r, bn+c] = sum_k W[bm+r, k] * X[b, bn+c, k]  (+ bias[bm+r])
// W: [M_total, 512] fp16 K-contiguous. X: [b, 4096, 512] fp16.
#define KC  64
#define LDT 72                              // KC + 8 pad; row stride 144 B
#define TILE_BYTES (128 * LDT * 2)          // 18432 B per tile
#define STAGE_BYTES (2 * TILE_BYTES)        // W, X  -> 36864 B
#define GEMM_SMEM  (2 * STAGE_BYTES)        // 73728 B (2 stages)

__global__ __launch_bounds__(256, 2) void gemm_mma(
    const h16* __restrict__ W, const h16* __restrict__ X,
    float* __restrict__ C, const float* __restrict__ bias, int M_total)
{
    extern __shared__ char sm[];
    uint32_t sbase = smem_to_u32(sm);

    int tid = threadIdx.x, wid = tid >> 5, lane = tid & 31;
    int b = blockIdx.z, bm = blockIdx.y * 128, bn = blockIdx.x * 128;
    int warp_m = (wid & 3) * 32;        // 4 warps along M
    int warp_n = (wid >> 2) * 64;       // 2 warps along N

    // global pointers in uint4 units (8 fp16); row pitch = 512/8 = 64
    const uint4* gW = (const uint4*)W + (size_t)bm * 64;
    const uint4* gX = (const uint4*)X + ((size_t)b * NPOS + bn) * 64;

    float acc[2][8][4];
    #pragma unroll
    for (int mt = 0; mt < 2; mt++)
        #pragma unroll
        for (int nt = 0; nt < 8; nt++)
            #pragma unroll
            for (int f = 0; f < 4; f++) acc[mt][nt][f] = 0.f;

    auto load_stage = [&](int s, int kc) {
        uint32_t ub = sbase + (uint32_t)s * STAGE_BYTES;
        #pragma unroll
        for (int l = 0; l < 4; l++) {
            int i = l * 256 + tid;
            int row = i >> 3, c8 = i & 7;
            size_t go = (size_t)row * 64 + kc * 8 + c8;
            uint32_t so = ub + (uint32_t)(row * LDT + c8 * 8) * 2;
            cp_async16(so,              gW + go);
            cp_async16(so + TILE_BYTES, gX + go);
        }
    };

    load_stage(0, 0);
    CP_COMMIT();

    for (int kc = 0; kc < 8; kc++) {
        if (kc + 1 < 8) {
            load_stage((kc + 1) & 1, kc + 1);
            CP_COMMIT();
            CP_WAIT(1);
        } else {
            CP_WAIT(0);
        }
        __syncthreads();

        uint32_t ub = sbase + (uint32_t)(kc & 1) * STAGE_BYTES;
        uint32_t uW = ub;
        uint32_t uX = ub + TILE_BYTES;

        #pragma unroll
        for (int kk = 0; kk < 4; kk++) {
            uint32_t ah[2][4];
            #pragma unroll
            for (int mt = 0; mt < 2; mt++) {
                uint32_t off = 2 * (uint32_t)((warp_m + mt * 16 + (lane & 15)) * LDT
                                              + kk * 16 + (lane >> 4) * 8);
                ldsm_x4(ah[mt][0], ah[mt][1], ah[mt][2], ah[mt][3], uW + off);
            }
            #pragma unroll
            for (int nt2 = 0; nt2 < 4; nt2++) {
                uint32_t off = 2 * (uint32_t)((warp_n + nt2 * 16 + (lane & 15)) * LDT
                                              + kk * 16 + (lane >> 4) * 8);
                uint32_t b0, b1, b2, b3;
                ldsm_x4(b0, b1, b2, b3, uX + off);
                #pragma unroll
                for (int mt = 0; mt < 2; mt++) {
                    mma16816(acc[mt][nt2 * 2 + 0], ah[mt], b0, b2);
                    mma16816(acc[mt][nt2 * 2 + 1], ah[mt], b1, b3);
                }
            }
        }
        __syncthreads();   // compute done before next prefetch overwrites
    }

    // writeout: c-frag rows r, r+8; cols 2*(lane%4), +1  -> float2 stores
    #pragma unroll
    for (int mt = 0; mt < 2; mt++) {
        int r0 = bm + warp_m + mt * 16 + (lane >> 2);
        float bb0 = bias ? bias[r0] : 0.f;
        float bb8 = bias ? bias[r0 + 8] : 0.f;
        #pragma unroll
        for (int nt = 0; nt < 8; nt++) {
            int col = bn + warp_n + nt * 8 + 2 * (lane & 3);
            float2 v0 = make_float2(acc[mt][nt][0] + bb0, acc[mt][nt][1] + bb0);
            float2 v1 = make_float2(acc[mt][nt][2] + bb8, acc[mt][nt][3] + bb8);
            *(float2*)&C[((size_t)b * M_total + r0    ) * NPOS + col] = v0;
            *(float2*)&C[((size_t)b * M_total + r0 + 8) * NPOS + col] = v1;
        }
    }
}

// ---------------- LN stats: mean/rstd over C per (b,p) ---------------------
__global__ __launch_bounds__(256) void ln_stats_kernel(
    const float* __restrict__ in, float* __restrict__ mean, float* __restrict__ rstd)
{
    int gid = blockIdx.x * 256 + threadIdx.x;
    int b = gid >> 12, p = gid & (NPOS - 1);
    const float* ip = in + (size_t)b * CDIM * NPOS + p;
    float s = 0.f, s2 = 0.f;
    #pragma unroll 8
    for (int c = 0; c < CDIM; c++) {
        float v = ip[(size_t)c * NPOS];
        s += v; s2 += v * v;
    }
    float m = s * (1.f / CDIM);
    float var = s2 * (1.f / CDIM) - m * m;
    mean[gid] = m;
    rstd[gid] = rsqrtf(var + EPSV);
}

// ---------------- normalize + transpose to channel-last fp16 ---------------
__global__ __launch_bounds__(256) void norm_transpose_kernel(
    const float* __restrict__ x, const float* __restrict__ g,
    const float* __restrict__ mean, const float* __restrict__ rstd,
    h16* __restrict__ xt)
{
    __shared__ float t[64][65];
    int b = blockIdx.z, c0 = blockIdx.y * 64, p0 = blockIdx.x * 64;
    int tid = threadIdx.x;
    #pragma unroll
    for (int l = 0; l < 16; l++) {
        int i = l * 256 + tid;
        int c = i >> 6, p = i & 63;
        float v = x[((size_t)b * CDIM + c0 + c) * NPOS + p0 + p];
        int sp = b * NPOS + p0 + p;
        t[p][c] = (v - mean[sp]) * rstd[sp] * g[c0 + c];
    }
    __syncthreads();
    #pragma unroll
    for (int l = 0; l < 16; l++) {
        int i = l * 256 + tid;
        int p = i >> 6, c = i & 63;
        size_t o = ((size_t)b * NPOS + p0 + p) * CDIM + c0 + c;
        xt[o] = __float2half(t[p][c]);
    }
}

// ---------------- fp32 -> fp16 convert (weights) ---------------------------
__global__ __launch_bounds__(256) void conv_fp16_kernel(
    const float* __restrict__ w, h16* __restrict__ h, int n)
{
    int i = blockIdx.x * 256 + threadIdx.x;
    if (i < n) h[i] = __float2half(w[i]);
}

// ---------------- warp reductions ------------------------------------------
__device__ __forceinline__ float warp_max(float v) {
    #pragma unroll
    for (int o = 16; o > 0; o >>= 1) v = fmaxf(v, __shfl_xor_sync(0xffffffffu, v, o));
    return v;
}
__device__ __forceinline__ float warp_sum(float v) {
    #pragma unroll
    for (int o = 16; o > 0; o >>= 1) v += __shfl_xor_sync(0xffffffffu, v, o);
    return v;
}

// ---------------- k row stats: max + 1/sum(exp) over n ---------------------
__global__ __launch_bounds__(256) void kstats_kernel(
    const float* __restrict__ qkv, float* __restrict__ kmx, float* __restrict__ krz)
{
    __shared__ float red[8];
    int row = blockIdx.x;                  // BATCH*HEADS*DH rows
    int i = row & (DH - 1);
    int m = (row >> 6) & (HEADS - 1);
    int b = row >> 9;
    const float* base = qkv + (size_t)b * O3 * NPOS + (size_t)(HID + m * DH + i) * NPOS;
    int t = threadIdx.x;
    int lane = t & 31, wid = t >> 5;

    float v[16];
    float mx = -CUDART_INF_F;
    #pragma unroll
    for (int u = 0; u < 16; u++) {
        v[u] = base[u * 256 + t];
        mx = fmaxf(mx, v[u]);
    }
    mx = warp_max(mx);
    if (lane == 0) red[wid] = mx;
    __syncthreads();
    mx = warp_max((lane < 8) ? red[lane] : -CUDART_INF_F);
    mx = __shfl_sync(0xffffffffu, mx, 0);

    float s = 0.f;
    #pragma unroll
    for (int u = 0; u < 16; u++) s += __expf(v[u] - mx);
    s = warp_sum(s);
    __syncthreads();
    if (lane == 0) red[wid] = s;
    __syncthreads();
    s = warp_sum((lane < 8) ? red[lane] : 0.f);
    s = __shfl_sync(0xffffffffu, s, 0);

    if (t == 0) { kmx[row] = mx; krz[row] = 1.f / s; }
}

// ---------------- zero ------------------------------------------------------
__global__ __launch_bounds__(256) void zero_kernel(float* __restrict__ p, int n)
{
    int i = blockIdx.x * 256 + threadIdx.x;
    if (i < n) p[i] = 0.f;
}

// -------- context[b,m,i,j] = (1/Z_i) sum_n exp(k[i,n]-mx_i) * v[j,n] -------
#define NSPLIT 4
__global__ __launch_bounds__(256) void context_kernel(
    const float* __restrict__ qkv, const float* __restrict__ kmx,
    const float* __restrict__ krz, float* __restrict__ ctx)
{
    __shared__ float Ks[64][65];
    __shared__ float Vs[64][65];
    int bm = blockIdx.x;
    int m = bm & (HEADS - 1);
    int b = bm >> 3;
    const float* kbase = qkv + (size_t)b * O3 * NPOS + (size_t)(HID     + m * DH) * NPOS;
    const float* vbase = qkv + (size_t)b * O3 * NPOS + (size_t)(2 * HID + m * DH) * NPOS;
    int tid = threadIdx.x;
    int ti = tid & 15, tj = tid >> 4;

    float acc[4][4];
    #pragma unroll
    for (int a = 0; a < 4; a++)
        #pragma unroll
        for (int c = 0; c < 4; c++) acc[a][c] = 0.f;

    int nsplit = NPOS / NSPLIT;
    int nstart = blockIdx.y * nsplit;
    for (int nc = 0; nc < nsplit; nc += 64) {
        int nb = nstart + nc;
        #pragma unroll
        for (int l = 0; l < 16; l++) {
            int idx = l * 256 + tid;
            int i = idx >> 6, nn = idx & 63;
            Ks[nn][i] = __expf(kbase[(size_t)i * NPOS + nb + nn] - kmx[bm * DH + i]);
            Vs[nn][i] = vbase[(size_t)i * NPOS + nb + nn];
        }
        __syncthreads();
        #pragma unroll 8
        for (int nn = 0; nn < 64; nn++) {
            float ka[4], vb[4];
            #pragma unroll
            for (int a = 0; a < 4; a++) ka[a] = Ks[nn][ti * 4 + a];
            #pragma unroll
            for (int c = 0; c < 4; c++) vb[c] = Vs[nn][tj * 4 + c];
            #pragma unroll
            for (int a = 0; a < 4; a++)
                #pragma unroll
                for (int c = 0; c < 4; c++) acc[a][c] += ka[a] * vb[c];
        }
        __syncthreads();
    }
    #pragma unroll
    for (int a = 0; a < 4; a++) {
        float rz = krz[bm * DH + ti * 4 + a];
        #pragma unroll
        for (int c = 0; c < 4; c++)
            atomicAdd(&ctx[(size_t)bm * DH * DH + (ti * 4 + a) * DH + (tj * 4 + c)],
                      acc[a][c] * rz);
    }
}

// -------- attn_out -> channel-last fp16, with INLINE q softmax -------------
// attn_t[b, n, m*64+j] = sum_i ctx[b,m,i,j] * softmax_i(q[b,m,i,n]) * scale
__global__ __launch_bounds__(128) void attnout_kernel(
    const float* __restrict__ qkv, const float* __restrict__ ctx,
    h16* __restrict__ at)
{
    __shared__ float cs[DH][DH];        // 16 KB
    __shared__ float stage[128][64];    // 32 KB (rotated to dodge bank conflicts)
    int bm = blockIdx.y;
    int m = bm & (HEADS - 1);
    int b = bm >> 3;
    const float* qbase = qkv + (size_t)b * O3 * NPOS + (size_t)(m * DH) * NPOS;
    int tid = threadIdx.x;

    #pragma unroll
    for (int l = 0; l < 32; l++)
        ((float*)cs)[l * 128 + tid] = ctx[(size_t)bm * DH * DH + l * 128 + tid];
    __syncthreads();

    int n0 = blockIdx.x * 128;
    int n = n0 + tid;

    // inline softmax over head-dim of q column
    float v[DH];
    float mx = -CUDART_INF_F;
    #pragma unroll
    for (int i = 0; i < DH; i++) {
        v[i] = qbase[(size_t)i * NPOS + n];
        mx = fmaxf(mx, v[i]);
    }
    float s = 0.f;
    #pragma unroll
    for (int i = 0; i < DH; i++) { v[i] = __expf(v[i] - mx); s += v[i]; }
    float r = QSCALE / s;

    float accj[DH];
    #pragma unroll
    for (int j = 0; j < DH; j++) accj[j] = 0.f;

    #pragma unroll 2
    for (int i = 0; i < DH; i++) {
        float qv = v[i];
        const float4* rowp = (const float4*)cs[i];
        #pragma unroll
        for (int j4 = 0; j4 < 16; j4++) {
            float4 c4 = rowp[j4];
            accj[j4 * 4 + 0] += c4.x * qv;
            accj[j4 * 4 + 1] += c4.y * qv;
            accj[j4 * 4 + 2] += c4.z * qv;
            accj[j4 * 4 + 3] += c4.w * qv;
        }
    }
    // rotated store (apply softmax denominator * scale here)
    #pragma unroll
    for (int j = 0; j < DH; j++) stage[tid][(j + tid) & 63] = accj[j] * r;
    __syncthreads();

    // coalesced channel-last fp16 write
    #pragma unroll
    for (int l = 0; l < 64; l++) {
        int idx = l * 128 + tid;
        int p = idx >> 6, j = idx & 63;
        size_t o = ((size_t)b * NPOS + n0 + p) * HID + m * DH + j;
        at[o] = __float2half(stage[p][(j + p) & 63]);
    }
}

// ---------------- final channel layernorm (channel-major, 2-pass) ----------
__global__ __launch_bounds__(256) void chan_ln_kernel(
    const float* __restrict__ in, const float* __restrict__ g,
    float* __restrict__ out)
{
    int gid = blockIdx.x * 256 + threadIdx.x;
    int b = gid >> 12;
    int p = gid & (NPOS - 1);
    const float* ip = in  + (size_t)b * CDIM * NPOS + p;
    float*       op = out + (size_t)b * CDIM * NPOS + p;

    float s = 0.f, s2 = 0.f;
    #pragma unroll 8
    for (int c = 0; c < CDIM; c++) {
        float v = ip[(size_t)c * NPOS];
        s += v; s2 += v * v;
    }
    float mean = s * (1.f / CDIM);
    float var = s2 * (1.f / CDIM) - mean * mean;
    float rstd = rsqrtf(var + EPSV);

    #pragma unroll 8
    for (int c = 0; c < CDIM; c++) {
        float v = ip[(size_t)c * NPOS];
        op[(size_t)c * NPOS] = (v - mean) * rstd * g[c];
    }
}

// ---------------- launch ---------------------------------------------------
extern "C" void kernel_launch(void* const* d_in, const int* in_sizes, int n_in,
                              void* d_out, int out_size)
{
    const float* x          = (const float*)d_in[0];
    const float* norm_g     = (const float*)d_in[1];
    const float* qkv_w      = (const float*)d_in[2];
    const float* out_w      = (const float*)d_in[3];
    const float* out_b      = (const float*)d_in[4];
    const float* out_norm_g = (const float*)d_in[5];
    float* out = (float*)d_out;

    float *mean, *rstd, *qkv, *ctx, *outpre, *kmx, *krz;
    h16 *xt, *at, *wq, *wo;
    cudaGetSymbolAddress((void**)&mean,   g_mean);
    cudaGetSymbolAddress((void**)&rstd,   g_rstd);
    cudaGetSymbolAddress((void**)&xt,     g_xt);
    cudaGetSymbolAddress((void**)&qkv,    g_qkv);
    cudaGetSymbolAddress((void**)&ctx,    g_ctx);
    cudaGetSymbolAddress((void**)&kmx,    g_kmx);
    cudaGetSymbolAddress((void**)&krz,    g_krz);
    cudaGetSymbolAddress((void**)&at,     g_at);
    cudaGetSymbolAddress((void**)&outpre, g_outpre);
    cudaGetSymbolAddress((void**)&wq,     g_wq);
    cudaGetSymbolAddress((void**)&wo,     g_wo);

    cudaFuncSetAttribute(gemm_mma, cudaFuncAttributeMaxDynamicSharedMemorySize,
                         GEMM_SMEM);

    // 1. LN stats + normalize-transpose (x -> xt fp16, channel-last)
    ln_stats_kernel<<<BATCH * NPOS / 256, 256>>>(x, mean, rstd);
    norm_transpose_kernel<<<dim3(NPOS / 64, CDIM / 64, BATCH), 256>>>(
        x, norm_g, mean, rstd, xt);

    // 2. weight converts (single fp16)
    conv_fp16_kernel<<<(O3 * CDIM) / 256, 256>>>(qkv_w, wq, O3 * CDIM);
    conv_fp16_kernel<<<(HID * CDIM) / 256, 256>>>(out_w, wo, HID * CDIM);

    // 3. qkv GEMM (tensor cores, single-product fp16, double-buffered)
    gemm_mma<<<dim3(NPOS / 128, O3 / 128, BATCH), 256, GEMM_SMEM>>>(
        wq, xt, qkv, nullptr, O3);

    // 4. k row stats (softmax_k folded into context)
    kstats_kernel<<<BATCH * HEADS * DH, 256>>>(qkv, kmx, krz);

    // 5. context = softmax(k) @ v^T  (exp applied inline, 1/Z in epilogue)
    int ctx_n = BATCH * HEADS * DH * DH;
    zero_kernel<<<(ctx_n + 255) / 256, 256>>>(ctx, ctx_n);
    context_kernel<<<dim3(BATCH * HEADS, NSPLIT), 256>>>(qkv, kmx, krz, ctx);

    // 6. attn out (inline q softmax) -> channel-last fp16
    attnout_kernel<<<dim3(NPOS / 128, BATCH * HEADS), 128>>>(qkv, ctx, at);

    // 7. out projection (tensor cores) + bias -> outpre (channel-major)
    gemm_mma<<<dim3(NPOS / 128, HID / 128, BATCH), 256, GEMM_SMEM>>>(
        wo, at, outpre, out_b, HID);

    // 8. final channel LN -> d_out
    chan_ln_kernel<<<BATCH * NPOS / 256, 256>>>(outpre, out_norm_g, out);
}